// round 1
// baseline (speedup 1.0000x reference)
#include <cuda_runtime.h>
#include <math.h>

// Causal depthwise conv1d: y[b,c,t] = sum_{k=0..23} w[c,k] * x[b,c,t-23+k]
// with w[c,k] = beta[c] * exp(log(max(alpha[c],1e-6))*k) * cosapprox(theta[c]*k)
// cosapprox(u) = 1 - u^2/2 + u^4/24  (matches reference _cos_approx exactly)

#define KSZ 24
#define T_LEN 3000
#define R_OUT 4
#define NTHREADS 768  // 750 compute-active (750*4 = 3000)

__global__ __launch_bounds__(NTHREADS)
void ssm4d_conv_kernel(const float* __restrict__ x,
                       const float* __restrict__ alpha,
                       const float* __restrict__ beta,
                       const float* __restrict__ theta,
                       float* __restrict__ y,
                       int C)
{
    // S layout: S[0..22] = 0 (causal left pad), S[23 + t] = x[row, t]
    // => y[t] = sum_k w[k] * S[t + k]
    __shared__ __align__(16) float S[T_LEN + KSZ];  // 3024 floats = 12096 B
    __shared__ float sw[KSZ];

    const int c = blockIdx.x;
    const int b = blockIdx.y;
    const int tid = threadIdx.x;
    const long rowbase = ((long)b * C + c) * (long)T_LEN;

    // ---- load row into shared (vectorized global load, scalar smem stores
    //      because data region starts at float offset 23) ----
    if (tid < KSZ - 1) S[tid] = 0.0f;
    if (tid < T_LEN / 4) {
        float4 v = reinterpret_cast<const float4*>(x + rowbase)[tid];
        int o = (KSZ - 1) + tid * 4;
        S[o + 0] = v.x; S[o + 1] = v.y; S[o + 2] = v.z; S[o + 3] = v.w;
    }

    // ---- per-channel weights (once per block) ----
    if (tid < KSZ) {
        float a  = alpha[c];
        float la = logf(fmaxf(a, 1e-6f));
        float d  = expf(la * (float)tid);
        float u  = theta[c] * (float)tid;
        float u2 = u * u;
        float ph = 1.0f - 0.5f * u2 + (u2 * u2) * (1.0f / 24.0f);
        sw[tid] = beta[c] * d * ph;
    }
    __syncthreads();

    if (tid * R_OUT < T_LEN) {
        // weights into registers (broadcast LDS, conflict-free)
        float w[KSZ];
#pragma unroll
        for (int k = 0; k < KSZ; k++) w[k] = sw[k];

        // input window: S[4*tid .. 4*tid+27] via 7 aligned LDS.128
        // (lane stride 16B -> conflict-free)
        float xv[R_OUT + KSZ + 4];  // 32 slots, use 28
        const float4* S4 = reinterpret_cast<const float4*>(&S[tid * R_OUT]);
#pragma unroll
        for (int j = 0; j < 7; j++) {
            float4 v = S4[j];
            xv[4 * j + 0] = v.x; xv[4 * j + 1] = v.y;
            xv[4 * j + 2] = v.z; xv[4 * j + 3] = v.w;
        }

        float acc0 = 0.f, acc1 = 0.f, acc2 = 0.f, acc3 = 0.f;
#pragma unroll
        for (int k = 0; k < KSZ; k++) {
            float wk = w[k];
            acc0 = fmaf(wk, xv[k + 0], acc0);
            acc1 = fmaf(wk, xv[k + 1], acc1);
            acc2 = fmaf(wk, xv[k + 2], acc2);
            acc3 = fmaf(wk, xv[k + 3], acc3);
        }

        float4 o;
        o.x = acc0; o.y = acc1; o.z = acc2; o.w = acc3;
        reinterpret_cast<float4*>(y + rowbase)[tid] = o;
    }
}

extern "C" void kernel_launch(void* const* d_in, const int* in_sizes, int n_in,
                              void* d_out, int out_size)
{
    const float* x     = (const float*)d_in[0];
    const float* alpha = (const float*)d_in[1];
    const float* beta  = (const float*)d_in[2];
    const float* theta = (const float*)d_in[3];
    float* y = (float*)d_out;

    const int C = in_sizes[1];                 // 1024
    const int B = in_sizes[0] / (C * T_LEN);   // 16

    dim3 grid(C, B);
    ssm4d_conv_kernel<<<grid, NTHREADS>>>(x, alpha, beta, theta, y, C);
}